// round 1
// baseline (speedup 1.0000x reference)
#include <cuda_runtime.h>
#include <cuda_bf16.h>
#include <math.h>

// ---------------------------------------------------------------------------
// Aggregator: relational graph attention
//   score_e   = leaky_relu( ego[head]^T @ W[etype] @ ego[tail] )   (bilinear!)
//   att_e     = exp(score_e) / segsum_head(exp(score))
//   out[n]    = segsum_head(att_e * ego[tail]) / max(deg(n), 1)
//
// N=100000, E=1250000, R=16, D=64 (capacities padded below).
// ---------------------------------------------------------------------------

#define E_CAP 1310720
#define N_CAP 131072

__device__ float g_exp[E_CAP];   // exp(score) per edge
__device__ float g_den[N_CAP];   // softmax denominator per head node
__device__ float g_cnt[N_CAP];   // edge count per head node

// ---------------------------------------------------------------------------
// Pass 0: zero output + per-node scratch (out is poisoned each run)
// ---------------------------------------------------------------------------
__global__ void zero_kernel(float* __restrict__ out, int N)
{
    int i = blockIdx.x * blockDim.x + threadIdx.x;
    if (i < N * 64) out[i] = 0.0f;
    if (i < N) { g_den[i] = 0.0f; g_cnt[i] = 0.0f; }
}

// ---------------------------------------------------------------------------
// Pass 1: scores. CTA is pinned to relation r = blockIdx.x & 15; W_r lives in
// registers (lane l holds rows l and l+32 -> 128 regs). Warps ballot-scan a
// contiguous edge slice and process matching edges collectively, with a
// 1-deep pipeline prefetching the next edge's head/tail embeddings.
// ---------------------------------------------------------------------------
__global__ __launch_bounds__(256) void pass1_scores(
    const float* __restrict__ ego,
    const float* __restrict__ Wg,
    const int*   __restrict__ heads,
    const int*   __restrict__ tails,
    const int*   __restrict__ etype,
    int E, int chunk)
{
    __shared__ float4 tbuf4[8][16];     // per-warp tail staging (64 floats)

    const int r    = blockIdx.x & 15;
    const int s    = blockIdx.x >> 4;
    const int lane = threadIdx.x & 31;
    const int warp = threadIdx.x >> 5;

    // --- load W_r rows (lane, lane+32) into registers -----------------------
    float w0[64], w1[64];
    {
        const float4* Wr0 = (const float4*)(Wg + (size_t)r * 4096 + (size_t)lane * 64);
        const float4* Wr1 = (const float4*)(Wg + (size_t)r * 4096 + (size_t)(lane + 32) * 64);
        #pragma unroll
        for (int i = 0; i < 16; i++) {
            float4 a = Wr0[i];
            w0[4*i+0] = a.x; w0[4*i+1] = a.y; w0[4*i+2] = a.z; w0[4*i+3] = a.w;
            float4 b = Wr1[i];
            w1[4*i+0] = b.x; w1[4*i+1] = b.y; w1[4*i+2] = b.z; w1[4*i+3] = b.w;
        }
    }

    const int e0 = s * chunk;
    const int e1 = min(E, e0 + chunk);
    float* tb = (float*)tbuf4[warp];

    for (int base = e0 + warp * 32; base < e1; base += 8 * 32) {
        int  e = base + lane;
        bool m = (e < e1) && (etype[e] == r);
        unsigned ball = __ballot_sync(0xffffffffu, m);
        int hl = 0, tl = 0;
        if (m) { hl = heads[e]; tl = tails[e]; }

        // 1-deep pipelined processing of matching edges
        int pe = -1, ph = 0;
        float pha = 0.f, phb = 0.f, pta = 0.f, ptb = 0.f;
        while (true) {
            int ne = -1, nh = 0;
            float nha = 0.f, nhb = 0.f, nta = 0.f, ntb = 0.f;
            if (ball) {
                int src = __ffs(ball) - 1;
                ball &= ball - 1;
                nh      = __shfl_sync(0xffffffffu, hl, src);
                int nt  = __shfl_sync(0xffffffffu, tl, src);
                ne      = base + src;
                const float* hp = ego + (size_t)nh * 64;
                const float* tp = ego + (size_t)nt * 64;
                nha = hp[lane]; nhb = hp[lane + 32];   // coalesced 128B pairs
                nta = tp[lane]; ntb = tp[lane + 32];
            }
            if (pe >= 0) {
                // stage tail into smem for broadcast reads
                __syncwarp();
                tb[lane] = pta; tb[lane + 32] = ptb;
                __syncwarp();
                float a0 = 0.f, a1 = 0.f, a2 = 0.f, a3 = 0.f;
                float b0 = 0.f, b1 = 0.f, b2 = 0.f, b3 = 0.f;
                #pragma unroll
                for (int q = 0; q < 16; q++) {
                    float4 t4 = tbuf4[warp][q];        // broadcast LDS.128
                    a0 += w0[4*q+0] * t4.x; a1 += w0[4*q+1] * t4.y;
                    a2 += w0[4*q+2] * t4.z; a3 += w0[4*q+3] * t4.w;
                    b0 += w1[4*q+0] * t4.x; b1 += w1[4*q+1] * t4.y;
                    b2 += w1[4*q+2] * t4.z; b3 += w1[4*q+3] * t4.w;
                }
                float part = pha * ((a0 + a1) + (a2 + a3))
                           + phb * ((b0 + b1) + (b2 + b3));
                #pragma unroll
                for (int o = 16; o > 0; o >>= 1)
                    part += __shfl_xor_sync(0xffffffffu, part, o);
                if (lane == 0) {
                    float sc = part > 0.f ? part : 0.01f * part;   // leaky_relu
                    float es = expf(sc);
                    g_exp[pe] = es;
                    atomicAdd(&g_den[ph], es);
                    atomicAdd(&g_cnt[ph], 1.0f);
                }
            }
            if (ne < 0) break;
            pe = ne; ph = nh;
            pha = nha; phb = nhb; pta = nta; ptb = ntb;
        }
    }
}

// ---------------------------------------------------------------------------
// Pass 2: att-weighted tail scatter. One warp per edge; lane l handles dims
// l and l+32 -> two coalesced red.global.add.f32 per lane.
// ---------------------------------------------------------------------------
__global__ __launch_bounds__(256) void pass2_scatter(
    const float* __restrict__ ego,
    const int*   __restrict__ heads,
    const int*   __restrict__ tails,
    float*       __restrict__ out,
    int E)
{
    int warp = (blockIdx.x * blockDim.x + threadIdx.x) >> 5;
    int lane = threadIdx.x & 31;
    if (warp >= E) return;
    int h = heads[warp];
    int t = tails[warp];
    float att = g_exp[warp] / g_den[h];
    const float* tp = ego + (size_t)t * 64;
    float* op = out + (size_t)h * 64;
    atomicAdd(&op[lane],      tp[lane]      * att);
    atomicAdd(&op[lane + 32], tp[lane + 32] * att);
}

// ---------------------------------------------------------------------------
// Pass 3: divide by per-node edge count (scatter_mean), clamped to 1.
// ---------------------------------------------------------------------------
__global__ void pass3_mean(float* __restrict__ out, int N)
{
    int i = blockIdx.x * blockDim.x + threadIdx.x;
    if (i < N * 64) {
        float c = g_cnt[i >> 6];
        out[i] = out[i] / fmaxf(c, 1.0f);
    }
}

// ---------------------------------------------------------------------------
extern "C" void kernel_launch(void* const* d_in, const int* in_sizes, int n_in,
                              void* d_out, int out_size)
{
    const float* ego = (const float*)d_in[0];   // [N,64] f32
    const float* Wg  = (const float*)d_in[1];   // [16,64,64] f32
    const int*   ei  = (const int*)d_in[2];     // [2,E] i32
    const int*   et  = (const int*)d_in[3];     // [E] i32
    float* out = (float*)d_out;

    int N = in_sizes[0] / 64;
    int E = in_sizes[3];
    const int* heads = ei;
    const int* tails = ei + E;

    int total = N * 64;
    zero_kernel<<<(total + 255) / 256, 256>>>(out, N);

    const int NSLICE = 64;
    int chunk = (E + NSLICE - 1) / NSLICE;
    pass1_scores<<<16 * NSLICE, 256>>>(ego, Wg, heads, tails, et, E, chunk);

    int ctas2 = (E + 7) / 8;   // 8 warps per 256-thread CTA, warp per edge
    pass2_scatter<<<ctas2, 256>>>(ego, heads, tails, out, E);

    pass3_mean<<<(total + 255) / 256, 256>>>(out, N);
}

// round 3
// speedup vs baseline: 2.4517x; 2.4517x over previous
#include <cuda_runtime.h>
#include <cuda_bf16.h>
#include <math.h>
#include <stdint.h>

// ---------------------------------------------------------------------------
// Aggregator: relational graph attention, tensor-core (warp mma.sync) version.
//   Y[r]     = ego @ W[r]            (bf16 hi/lo split HMMA, fp32 accumulate)
//   s_e      = leaky_relu( Y[et_e, h_e] . ego[t_e] )
//   out[n]   = sum_e exp(s_e) * ego[t_e]  /  ( den[n] * max(cnt[n],1) )
// den[n] = sum exp over head==n (softmax denom hoisted into the epilogue).
// ---------------------------------------------------------------------------

#define N_CAP   131072
#define YROWS   102400               // >= N, multiple of 128
__device__ float  g_Y[16u * YROWS * 64u];   // [R, N, 64]
__device__ float2 g_dencnt[N_CAP];          // (den, cnt) per head node

__device__ __forceinline__ uint32_t smem_u32(const void* p) {
    uint32_t a;
    asm("{ .reg .u64 t; cvta.to.shared.u64 t, %1; cvt.u32.u64 %0, t; }"
        : "=r"(a) : "l"(p));
    return a;
}

__device__ __forceinline__ void ldm_x4(uint32_t* r, uint32_t addr) {
    asm volatile("ldmatrix.sync.aligned.m8n8.x4.shared.b16 {%0,%1,%2,%3}, [%4];"
                 : "=r"(r[0]), "=r"(r[1]), "=r"(r[2]), "=r"(r[3]) : "r"(addr));
}

__device__ __forceinline__ void mma_bf16(float* c, const uint32_t* a,
                                         uint32_t b0, uint32_t b1) {
    asm volatile(
        "mma.sync.aligned.m16n8k16.row.col.f32.bf16.bf16.f32 "
        "{%0,%1,%2,%3}, {%4,%5,%6,%7}, {%8,%9}, {%0,%1,%2,%3};"
        : "+f"(c[0]), "+f"(c[1]), "+f"(c[2]), "+f"(c[3])
        : "r"(a[0]), "r"(a[1]), "r"(a[2]), "r"(a[3]), "r"(b0), "r"(b1));
}

__device__ __forceinline__ uint32_t pack_bf2(float x0, float x1,
                                             float* r0, float* r1) {
    __nv_bfloat16 h0 = __float2bfloat16(x0);
    __nv_bfloat16 h1 = __float2bfloat16(x1);
    *r0 = x0 - __bfloat162float(h0);
    *r1 = x1 - __bfloat162float(h1);
    return ((uint32_t)__bfloat16_as_ushort(h1) << 16)
         | (uint32_t)__bfloat16_as_ushort(h0);
}
__device__ __forceinline__ uint32_t pack2(float x0, float x1) {
    return ((uint32_t)__bfloat16_as_ushort(__float2bfloat16(x1)) << 16)
         | (uint32_t)__bfloat16_as_ushort(__float2bfloat16(x0));
}

// smem layout (dynamic): bf16 tiles, row stride 72 halves (144B) so ldmatrix
// 8-row phases land on distinct bank groups.
#define AS      72
#define A_HI    0
#define A_LO    18432
#define B_HI    36864
#define B_LO    46080
#define SMEM_SZ 55296

// ============================ kernels ======================================

__global__ void zero_kernel(float* __restrict__ out, int N)
{
    int i = blockIdx.x * blockDim.x + threadIdx.x;
    if (i < N * 64) out[i] = 0.0f;
    if (i < N) g_dencnt[i] = make_float2(0.0f, 0.0f);
}

// ---- GEMM: Y[r] = X @ W[r]; one 128-row tile per CTA, loop over relations -
__global__ __launch_bounds__(256) void gemm_transform(
    const float* __restrict__ ego, const float* __restrict__ Wg, int N)
{
    extern __shared__ __align__(16) char sm[];
    __nv_bfloat16* sh = (__nv_bfloat16*)sm;
    const uint32_t smb = smem_u32(sm);

    const int tid  = threadIdx.x;
    const int wid  = tid >> 5;
    const int lane = tid & 31;
    const int tile = blockIdx.x;
    const int rows = min(128, N - tile * 128);

    // --- stage A tile (ego rows) as bf16 hi/lo, zero-padded ----------------
    for (int i = tid * 2; i < 128 * 64; i += 512) {
        int row = i >> 6, col = i & 63;
        float v0 = 0.f, v1 = 0.f;
        if (row < rows) {
            const float2 v = *(const float2*)(ego + ((size_t)(tile * 128 + row)) * 64 + col);
            v0 = v.x; v1 = v.y;
        }
        float l0, l1;
        uint32_t hi = pack_bf2(v0, v1, &l0, &l1);
        *(uint32_t*)(sh + (A_HI / 2) + row * AS + col) = hi;
        *(uint32_t*)(sh + (A_LO / 2) + row * AS + col) = pack2(l0, l1);
    }
    __syncthreads();

    // --- per-warp A fragments (16 rows x K=64), loaded once ----------------
    const int m0 = wid * 16;
    const int frow = (lane & 7) + ((lane >> 3) & 1) * 8;
    const int fcol = (lane >> 4) * 8;
    uint32_t Ah[4][4], Al[4][4];
    #pragma unroll
    for (int kt = 0; kt < 4; kt++) {
        uint32_t off = (uint32_t)((m0 + frow) * AS + kt * 16 + fcol) * 2;
        ldm_x4(Ah[kt], smb + A_HI + off);
        ldm_x4(Al[kt], smb + A_LO + off);
    }

    const int g = lane >> 2;          // output row group
    const int tq = lane & 3;          // output col pair

    for (int r = 0; r < 16; r++) {
        // stage B = W_r^T as bf16 hi/lo  (Wt[n][k] = W[k][n])
        for (int i = tid * 2; i < 4096; i += 512) {
            int k = i >> 6, n = i & 63;                 // coalesced W read
            const float2 v = *(const float2*)(Wg + (size_t)r * 4096 + i);
            float l0, l1;
            uint32_t hi = pack_bf2(v.x, v.y, &l0, &l1);
            uint32_t lo = pack2(l0, l1);
            // scatter-transpose into smem (bf16 scalar stores)
            sh[(B_HI / 2) + n * AS + k]       = *(__nv_bfloat16*)&hi;
            sh[(B_HI / 2) + (n + 1) * AS + k] = *((__nv_bfloat16*)&hi + 1);
            sh[(B_LO / 2) + n * AS + k]       = *(__nv_bfloat16*)&lo;
            sh[(B_LO / 2) + (n + 1) * AS + k] = *((__nv_bfloat16*)&lo + 1);
        }
        __syncthreads();

        float acc[8][4];
        #pragma unroll
        for (int i = 0; i < 8; i++)
            #pragma unroll
            for (int j = 0; j < 4; j++) acc[i][j] = 0.f;

        #pragma unroll
        for (int nt = 0; nt < 4; nt++) {
            #pragma unroll
            for (int kt = 0; kt < 4; kt++) {
                uint32_t boff = (uint32_t)((nt * 16 + frow) * AS + kt * 16 + fcol) * 2;
                uint32_t Bh[4], Bl[4];
                ldm_x4(Bh, smb + B_HI + boff);
                mma_bf16(acc[2 * nt],     Ah[kt], Bh[0], Bh[2]);
                mma_bf16(acc[2 * nt + 1], Ah[kt], Bh[1], Bh[3]);
                mma_bf16(acc[2 * nt],     Al[kt], Bh[0], Bh[2]);
                mma_bf16(acc[2 * nt + 1], Al[kt], Bh[1], Bh[3]);
                ldm_x4(Bl, smb + B_LO + boff);
                mma_bf16(acc[2 * nt],     Ah[kt], Bl[0], Bl[2]);
                mma_bf16(acc[2 * nt + 1], Ah[kt], Bl[1], Bl[3]);
            }
        }

        // store Y tile: float2 per (row, colpair) — full 32B sectors
        int row0 = m0 + g;
        int node0 = tile * 128 + row0;
        #pragma unroll
        for (int nt8 = 0; nt8 < 8; nt8++) {
            int col = nt8 * 8 + tq * 2;
            if (row0 < rows)
                *(float2*)(g_Y + ((size_t)r * N + node0) * 64 + col)
                    = make_float2(acc[nt8][0], acc[nt8][1]);
            if (row0 + 8 < rows)
                *(float2*)(g_Y + ((size_t)r * N + node0 + 8) * 64 + col)
                    = make_float2(acc[nt8][2], acc[nt8][3]);
        }
        __syncthreads();   // done with B before next relation restages
    }
}

// ---- fused edge pass: score, exp, den/cnt, weighted scatter ---------------
__global__ __launch_bounds__(256) void edge_pass(
    const float* __restrict__ ego,
    const int*   __restrict__ heads,
    const int*   __restrict__ tails,
    const int*   __restrict__ etype,
    float*       __restrict__ out,
    int N, int E)
{
    const int gw   = (blockIdx.x * 256 + threadIdx.x) >> 5;
    const int lane = threadIdx.x & 31;
    const int half = lane >> 4;
    const int l2   = lane & 15;
    const unsigned hmask = 0xFFFFu << (half * 16);

    long e = (long)gw * 2 + half;
    if (e >= E) return;

    const int h = heads[e];
    const int t = tails[e];
    const int r = etype[e];

    float4 y4 = ((const float4*)g_Y)[((size_t)r * N + h) * 16 + l2];
    float4 t4 = ((const float4*)ego)[(size_t)t * 16 + l2];

    float part = y4.x * t4.x + y4.y * t4.y + y4.z * t4.z + y4.w * t4.w;
    part += __shfl_xor_sync(hmask, part, 1);
    part += __shfl_xor_sync(hmask, part, 2);
    part += __shfl_xor_sync(hmask, part, 4);
    part += __shfl_xor_sync(hmask, part, 8);

    float sc = part > 0.0f ? part : 0.01f * part;     // leaky_relu
    float es = __expf(sc);

    if (l2 == 0) {
        float2* dc = &g_dencnt[h];
        asm volatile("red.global.add.v2.f32 [%0], {%1, %2};"
                     :: "l"(dc), "f"(es), "f"(1.0f) : "memory");
    }
    float* op = out + (size_t)h * 64 + l2 * 4;
    asm volatile("red.global.add.v4.f32 [%0], {%1, %2, %3, %4};"
                 :: "l"(op), "f"(es * t4.x), "f"(es * t4.y),
                    "f"(es * t4.z), "f"(es * t4.w) : "memory");
}

// ---- epilogue: divide by den * max(cnt,1) ---------------------------------
__global__ void pass3_mean(float* __restrict__ out, int N)
{
    int i = blockIdx.x * blockDim.x + threadIdx.x;
    if (i < N * 64) {
        float2 dc = g_dencnt[i >> 6];
        out[i] = (dc.y > 0.0f) ? out[i] / (dc.x * dc.y) : 0.0f;
    }
}

// ---------------------------------------------------------------------------
extern "C" void kernel_launch(void* const* d_in, const int* in_sizes, int n_in,
                              void* d_out, int out_size)
{
    const float* ego = (const float*)d_in[0];   // [N,64] f32
    const float* Wg  = (const float*)d_in[1];   // [16,64,64] f32
    const int*   ei  = (const int*)d_in[2];     // [2,E] i32
    const int*   et  = (const int*)d_in[3];     // [E] i32
    float* out = (float*)d_out;

    const int N = in_sizes[0] / 64;
    const int E = in_sizes[3];
    const int* heads = ei;
    const int* tails = ei + E;

    cudaFuncSetAttribute(gemm_transform,
                         cudaFuncAttributeMaxDynamicSharedMemorySize, SMEM_SZ);

    const int total = N * 64;
    zero_kernel<<<(total + 255) / 256, 256>>>(out, N);

    const int tiles = (N + 127) / 128;
    gemm_transform<<<tiles, 256, SMEM_SZ>>>(ego, Wg, N);

    edge_pass<<<(E + 15) / 16, 256>>>(ego, heads, tails, et, out, N, E);

    pass3_mean<<<(total + 255) / 256, 256>>>(out, N);
}

// round 4
// speedup vs baseline: 3.2929x; 1.3431x over previous
#include <cuda_runtime.h>
#include <cuda_bf16.h>
#include <cuda_fp16.h>
#include <math.h>
#include <stdint.h>

// ---------------------------------------------------------------------------
// Aggregator: relational graph attention, tensor-core (warp mma.sync) version.
//   Y[r]     = ego @ W[r]     (bf16 hi/lo split HMMA, fp32 acc, stored fp16)
//   s_e      = leaky_relu( Y[et_e, h_e] . ego[t_e] )
//   out[n]   = sum_e exp(s_e) * ego[t_e]  /  ( den[n] * max(cnt[n],1) )
// den[n] = sum exp over head==n (softmax denom hoisted into the epilogue).
// ---------------------------------------------------------------------------

#define N_CAP   131072
#define YROWS   102400               // >= N, multiple of 128
__device__ __half g_Yh[16u * YROWS * 64u];     // [R, N, 64] fp16
__device__ float2 g_dencnt[N_CAP];             // (den, cnt) per head node

// pre-transposed W (row n, col k), padded row stride AS, bf16 hi/lo
#define AS 72
__device__ __nv_bfloat16 g_Wt_hi[16 * 64 * AS];
__device__ __nv_bfloat16 g_Wt_lo[16 * 64 * AS];

__device__ __forceinline__ uint32_t smem_u32(const void* p) {
    uint32_t a;
    asm("{ .reg .u64 t; cvta.to.shared.u64 t, %1; cvt.u32.u64 %0, t; }"
        : "=r"(a) : "l"(p));
    return a;
}
__device__ __forceinline__ void ldm_x4(uint32_t* r, uint32_t addr) {
    asm volatile("ldmatrix.sync.aligned.m8n8.x4.shared.b16 {%0,%1,%2,%3}, [%4];"
                 : "=r"(r[0]), "=r"(r[1]), "=r"(r[2]), "=r"(r[3]) : "r"(addr));
}
__device__ __forceinline__ void mma_bf16(float* c, const uint32_t* a,
                                         uint32_t b0, uint32_t b1) {
    asm volatile(
        "mma.sync.aligned.m16n8k16.row.col.f32.bf16.bf16.f32 "
        "{%0,%1,%2,%3}, {%4,%5,%6,%7}, {%8,%9}, {%0,%1,%2,%3};"
        : "+f"(c[0]), "+f"(c[1]), "+f"(c[2]), "+f"(c[3])
        : "r"(a[0]), "r"(a[1]), "r"(a[2]), "r"(a[3]), "r"(b0), "r"(b1));
}
__device__ __forceinline__ uint32_t pack_bf2(float x0, float x1,
                                             float* r0, float* r1) {
    __nv_bfloat16 h0 = __float2bfloat16(x0);
    __nv_bfloat16 h1 = __float2bfloat16(x1);
    *r0 = x0 - __bfloat162float(h0);
    *r1 = x1 - __bfloat162float(h1);
    return ((uint32_t)__bfloat16_as_ushort(h1) << 16)
         | (uint32_t)__bfloat16_as_ushort(h0);
}
__device__ __forceinline__ uint32_t pack2(float x0, float x1) {
    return ((uint32_t)__bfloat16_as_ushort(__float2bfloat16(x1)) << 16)
         | (uint32_t)__bfloat16_as_ushort(__float2bfloat16(x0));
}

// smem layout (bytes): bf16 tiles, row stride AS=72 halves (144B) so ldmatrix
// 8-row phases hit distinct bank groups.
#define A_HI    0
#define A_LO    18432
#define B_HI    36864
#define B_LO    46080
#define SMEM_SZ 55296

// ============================ kernels ======================================

// ---- one-time W transpose + bf16 hi/lo split (grid = 16 relations) --------
__global__ __launch_bounds__(256) void wt_prep(const float* __restrict__ Wg)
{
    const int r = blockIdx.x;
    for (int idx = threadIdx.x; idx < 4096; idx += 256) {
        int k = idx >> 6, n = idx & 63;             // W[k][n], coalesced read
        float v = Wg[(size_t)r * 4096 + idx];
        __nv_bfloat16 hi = __float2bfloat16(v);
        __nv_bfloat16 lo = __float2bfloat16(v - __bfloat162float(hi));
        g_Wt_hi[(size_t)r * 64 * AS + n * AS + k] = hi;
        g_Wt_lo[(size_t)r * 64 * AS + n * AS + k] = lo;
    }
}

// ---- zero out + dencnt, vectorized ----------------------------------------
__global__ void zero_kernel(float4* __restrict__ out4, int n_out4, int n_dc4)
{
    int i = blockIdx.x * blockDim.x + threadIdx.x;
    float4 z = make_float4(0.f, 0.f, 0.f, 0.f);
    if (i < n_out4) out4[i] = z;
    if (i < n_dc4) ((float4*)g_dencnt)[i] = z;
}

// ---- GEMM: Y[r] = X @ W[r]; one 128-row tile per CTA, loop over relations -
__global__ __launch_bounds__(256) void gemm_transform(
    const float* __restrict__ ego, int N)
{
    extern __shared__ __align__(16) char sm[];
    __nv_bfloat16* sh = (__nv_bfloat16*)sm;
    const uint32_t smb = smem_u32(sm);

    const int tid  = threadIdx.x;
    const int wid  = tid >> 5;
    const int lane = tid & 31;
    const int tile = blockIdx.x;
    const int rows = min(128, N - tile * 128);

    // --- stage A tile (ego rows) as bf16 hi/lo, zero-padded ----------------
    for (int i = tid * 2; i < 128 * 64; i += 512) {
        int row = i >> 6, col = i & 63;
        float v0 = 0.f, v1 = 0.f;
        if (row < rows) {
            const float2 v = *(const float2*)(ego + ((size_t)(tile * 128 + row)) * 64 + col);
            v0 = v.x; v1 = v.y;
        }
        float l0, l1;
        uint32_t hi = pack_bf2(v0, v1, &l0, &l1);
        *(uint32_t*)(sh + (A_HI / 2) + row * AS + col) = hi;
        *(uint32_t*)(sh + (A_LO / 2) + row * AS + col) = pack2(l0, l1);
    }
    __syncthreads();

    // --- per-warp A fragments (16 rows x K=64), loaded once ----------------
    const int m0 = wid * 16;
    const int frow = (lane & 7) + ((lane >> 3) & 1) * 8;
    const int fcol = (lane >> 4) * 8;
    uint32_t Ah[4][4], Al[4][4];
    #pragma unroll
    for (int kt = 0; kt < 4; kt++) {
        uint32_t off = (uint32_t)((m0 + frow) * AS + kt * 16 + fcol) * 2;
        ldm_x4(Ah[kt], smb + A_HI + off);
        ldm_x4(Al[kt], smb + A_LO + off);
    }

    const int g  = lane >> 2;         // output row group
    const int tq = lane & 3;          // output col pair

    for (int r = 0; r < 16; r++) {
        // stage B = pre-transposed W_r (vector copies, no transpose work)
        {
            const uint4* src_hi = (const uint4*)(g_Wt_hi + (size_t)r * 64 * AS);
            const uint4* src_lo = (const uint4*)(g_Wt_lo + (size_t)r * 64 * AS);
            uint4* dst_hi = (uint4*)(sm + B_HI);
            uint4* dst_lo = (uint4*)(sm + B_LO);
            #pragma unroll
            for (int i = tid; i < 576; i += 256) {     // 64 rows * 9 uint4
                dst_hi[i] = src_hi[i];
                dst_lo[i] = src_lo[i];
            }
        }
        __syncthreads();

        float acc[8][4];
        #pragma unroll
        for (int i = 0; i < 8; i++)
            #pragma unroll
            for (int j = 0; j < 4; j++) acc[i][j] = 0.f;

        #pragma unroll
        for (int nt = 0; nt < 4; nt++) {
            #pragma unroll
            for (int kt = 0; kt < 4; kt++) {
                uint32_t boff = (uint32_t)((nt * 16 + frow) * AS + kt * 16 + fcol) * 2;
                uint32_t Bh[4], Bl[4];
                ldm_x4(Bh, smb + B_HI + boff);
                mma_bf16(acc[2 * nt],     Ah[kt], Bh[0], Bh[2]);
                mma_bf16(acc[2 * nt + 1], Ah[kt], Bh[1], Bh[3]);
                mma_bf16(acc[2 * nt],     Al[kt], Bh[0], Bh[2]);
                mma_bf16(acc[2 * nt + 1], Al[kt], Bh[1], Bh[3]);
                ldm_x4(Bl, smb + B_LO + boff);
                mma_bf16(acc[2 * nt],     Ah[kt], Bl[0], Bl[2]);
                mma_bf16(acc[2 * nt + 1], Ah[kt], Bl[1], Bl[3]);
            }
        }

        // store Y tile as fp16 (uint = half2 per (row, colpair))
        int row0  = m0 + g;
        int node0 = tile * 128 + row0;
        #pragma unroll
        for (int nt8 = 0; nt8 < 8; nt8++) {
            int col = nt8 * 8 + tq * 2;
            if (row0 < rows) {
                __half2 h = __floats2half2_rn(acc[nt8][0], acc[nt8][1]);
                *(uint32_t*)(g_Yh + ((size_t)r * N + node0) * 64 + col)
                    = *(uint32_t*)&h;
            }
            if (row0 + 8 < rows) {
                __half2 h = __floats2half2_rn(acc[nt8][2], acc[nt8][3]);
                *(uint32_t*)(g_Yh + ((size_t)r * N + node0 + 8) * 64 + col)
                    = *(uint32_t*)&h;
            }
        }
        __syncthreads();   // B consumed before next relation restages
    }
}

// ---- fused edge pass: score, exp, den/cnt, weighted scatter ---------------
__global__ __launch_bounds__(256) void edge_pass(
    const float* __restrict__ ego,
    const int*   __restrict__ heads,
    const int*   __restrict__ tails,
    const int*   __restrict__ etype,
    float*       __restrict__ out,
    int N, int E)
{
    const int gw   = (blockIdx.x * 256 + threadIdx.x) >> 5;
    const int lane = threadIdx.x & 31;
    const int half = lane >> 4;
    const int l2   = lane & 15;
    const unsigned hmask = 0xFFFFu << (half * 16);

    long e = (long)gw * 2 + half;
    if (e >= E) return;

    const int h = heads[e];
    const int t = tails[e];
    const int r = etype[e];

    // Y row gather: 128B fp16 row, uint2 (4 halves) per lane
    uint2 yv = *(const uint2*)(g_Yh + ((size_t)r * N + h) * 64 + l2 * 4);
    __half2 y01 = *(__half2*)&yv.x;
    __half2 y23 = *(__half2*)&yv.y;
    float2 f01 = __half22float2(y01);
    float2 f23 = __half22float2(y23);

    float4 t4 = ((const float4*)ego)[(size_t)t * 16 + l2];

    float part = f01.x * t4.x + f01.y * t4.y + f23.x * t4.z + f23.y * t4.w;
    part += __shfl_xor_sync(hmask, part, 1);
    part += __shfl_xor_sync(hmask, part, 2);
    part += __shfl_xor_sync(hmask, part, 4);
    part += __shfl_xor_sync(hmask, part, 8);

    float sc = part > 0.0f ? part : 0.01f * part;     // leaky_relu
    float es = __expf(sc);

    if (l2 == 0) {
        float2* dc = &g_dencnt[h];
        asm volatile("red.global.add.v2.f32 [%0], {%1, %2};"
                     :: "l"(dc), "f"(es), "f"(1.0f) : "memory");
    }
    float* op = out + (size_t)h * 64 + l2 * 4;
    asm volatile("red.global.add.v4.f32 [%0], {%1, %2, %3, %4};"
                 :: "l"(op), "f"(es * t4.x), "f"(es * t4.y),
                    "f"(es * t4.z), "f"(es * t4.w) : "memory");
}

// ---- epilogue: divide by den * max(cnt,1), float4 per thread --------------
__global__ void pass3_mean(float4* __restrict__ out4, int N)
{
    int i = blockIdx.x * blockDim.x + threadIdx.x;    // one float4 (4 elems)
    if (i < N * 16) {
        float2 dc = g_dencnt[i >> 4];
        float s = (dc.y > 0.0f) ? __frcp_rn(dc.x * dc.y) : 0.0f;
        float4 v = out4[i];
        v.x *= s; v.y *= s; v.z *= s; v.w *= s;
        out4[i] = v;
    }
}

// ---------------------------------------------------------------------------
extern "C" void kernel_launch(void* const* d_in, const int* in_sizes, int n_in,
                              void* d_out, int out_size)
{
    const float* ego = (const float*)d_in[0];   // [N,64] f32
    const float* Wg  = (const float*)d_in[1];   // [16,64,64] f32
    const int*   ei  = (const int*)d_in[2];     // [2,E] i32
    const int*   et  = (const int*)d_in[3];     // [E] i32
    float* out = (float*)d_out;

    const int N = in_sizes[0] / 64;
    const int E = in_sizes[3];
    const int* heads = ei;
    const int* tails = ei + E;

    cudaFuncSetAttribute(gemm_transform,
                         cudaFuncAttributeMaxDynamicSharedMemorySize, SMEM_SZ);

    wt_prep<<<16, 256>>>(Wg);

    const int n_out4 = N * 16;                  // out as float4
    const int n_dc4  = (N * 2 + 3) / 4;         // dencnt as float4
    zero_kernel<<<(n_out4 + 255) / 256, 256>>>((float4*)out, n_out4, n_dc4);

    const int tiles = (N + 127) / 128;
    gemm_transform<<<tiles, 256, SMEM_SZ>>>(ego, N);

    edge_pass<<<(E + 15) / 16, 256>>>(ego, heads, tails, et, out, N, E);

    pass3_mean<<<(n_out4 + 255) / 256, 256>>>((float4*)out, N);
}

// round 5
// speedup vs baseline: 4.3038x; 1.3070x over previous
#include <cuda_runtime.h>
#include <cuda_bf16.h>
#include <cuda_fp16.h>
#include <math.h>
#include <stdint.h>

// ---------------------------------------------------------------------------
// Aggregator: relational graph attention, tensor-core (warp mma.sync) version.
//   Y[r]     = ego @ W[r]            (bf16 HMMA, fp32 accumulate, fp16 store)
//   s_e      = leaky_relu( Y[et_e, h_e] . ego[t_e] )
//   out[n]   = sum_e exp(s_e) * ego[t_e]  /  ( den[n] * max(cnt[n],1) )
// den[n] = sum exp over head==n (softmax denom hoisted into the epilogue).
// ---------------------------------------------------------------------------

#define N_CAP   131072
#define YROWS   102400               // >= N, multiple of 256
__device__ __half g_Yh[16u * YROWS * 64u];     // [R, N, 64] fp16
__device__ float2 g_dencnt[N_CAP];             // (den, cnt) per head node

// pre-transposed W (row n, col k), padded row stride AS, bf16
#define AS 72
__device__ __nv_bfloat16 g_Wt[16 * 64 * AS];

__device__ __forceinline__ uint32_t smem_u32(const void* p) {
    uint32_t a;
    asm("{ .reg .u64 t; cvta.to.shared.u64 t, %1; cvt.u32.u64 %0, t; }"
        : "=r"(a) : "l"(p));
    return a;
}
__device__ __forceinline__ void ldm_x4(uint32_t* r, uint32_t addr) {
    asm volatile("ldmatrix.sync.aligned.m8n8.x4.shared.b16 {%0,%1,%2,%3}, [%4];"
                 : "=r"(r[0]), "=r"(r[1]), "=r"(r[2]), "=r"(r[3]) : "r"(addr));
}
__device__ __forceinline__ void mma_bf16(float* c, const uint32_t* a,
                                         uint32_t b0, uint32_t b1) {
    asm volatile(
        "mma.sync.aligned.m16n8k16.row.col.f32.bf16.bf16.f32 "
        "{%0,%1,%2,%3}, {%4,%5,%6,%7}, {%8,%9}, {%0,%1,%2,%3};"
        : "+f"(c[0]), "+f"(c[1]), "+f"(c[2]), "+f"(c[3])
        : "r"(a[0]), "r"(a[1]), "r"(a[2]), "r"(a[3]), "r"(b0), "r"(b1));
}
__device__ __forceinline__ uint32_t pack2(float x0, float x1) {
    return ((uint32_t)__bfloat16_as_ushort(__float2bfloat16(x1)) << 16)
         | (uint32_t)__bfloat16_as_ushort(__float2bfloat16(x0));
}

// smem layout (bytes): A = 256 rows x AS halves, then B = 64 rows x AS halves
#define A_OFF   0
#define B_OFF   36864
#define SMEM_SZ (36864 + 9216 + 128)

// ============================ kernels ======================================

// ---- one-time W transpose to bf16 (grid = 16 relations) -------------------
__global__ __launch_bounds__(256) void wt_prep(const float* __restrict__ Wg)
{
    const int r = blockIdx.x;
    for (int idx = threadIdx.x; idx < 4096; idx += 256) {
        int k = idx >> 6, n = idx & 63;             // W[k][n], coalesced read
        float v = Wg[(size_t)r * 4096 + idx];
        g_Wt[r * 64 * AS + n * AS + k] = __float2bfloat16(v);
    }
}

// ---- zero out + dencnt, vectorized ----------------------------------------
__global__ void zero_kernel(float4* __restrict__ out4, int n_out4, int n_dc4)
{
    int i = blockIdx.x * blockDim.x + threadIdx.x;
    float4 z = make_float4(0.f, 0.f, 0.f, 0.f);
    if (i < n_out4) out4[i] = z;
    if (i < n_dc4) ((float4*)g_dencnt)[i] = z;
}

// ---- GEMM: Y[r] = X @ W[r]; 256-row tile per CTA, loop over 16 relations --
__global__ __launch_bounds__(256) void gemm_transform(
    const float* __restrict__ ego, int N)
{
    extern __shared__ __align__(16) char sm[];
    __nv_bfloat16* sh = (__nv_bfloat16*)sm;
    const uint32_t smb = smem_u32(sm);

    const int tid  = threadIdx.x;
    const int wid  = tid >> 5;
    const int lane = tid & 31;
    const int tile = blockIdx.x;
    const int rows = min(256, N - tile * 256);

    // --- stage A tile (ego rows) as bf16, zero-padded ----------------------
    for (int i = tid * 2; i < 256 * 64; i += 512) {
        int row = i >> 6, col = i & 63;
        float v0 = 0.f, v1 = 0.f;
        if (row < rows) {
            const float2 v = *(const float2*)(ego + ((size_t)(tile * 256 + row)) * 64 + col);
            v0 = v.x; v1 = v.y;
        }
        *(uint32_t*)(sh + row * AS + col) = pack2(v0, v1);
    }
    __syncthreads();

    // --- per-warp A fragments: 32 rows (2 x 16) x K=64, loaded once --------
    const int m0   = wid * 32;
    const int frow = (lane & 7) + ((lane >> 3) & 1) * 8;
    const int fcol = (lane >> 4) * 8;
    uint32_t Af[2][4][4];
    #pragma unroll
    for (int rt = 0; rt < 2; rt++)
        #pragma unroll
        for (int kt = 0; kt < 4; kt++) {
            uint32_t off = (uint32_t)((m0 + rt * 16 + frow) * AS + kt * 16 + fcol) * 2;
            ldm_x4(Af[rt][kt], smb + A_OFF + off);
        }

    const int g  = lane >> 2;         // output row within 8-group
    const int tq = lane & 3;          // output col pair

    for (int r = 0; r < 16; r++) {
        // stage B = pre-transposed W_r (pure vector copies)
        {
            const uint4* src = (const uint4*)(g_Wt + r * 64 * AS);
            uint4* dst = (uint4*)(sm + B_OFF);
            #pragma unroll
            for (int i = tid; i < 576; i += 256) dst[i] = src[i];
        }
        __syncthreads();

        float acc[2][8][4];
        #pragma unroll
        for (int rt = 0; rt < 2; rt++)
            #pragma unroll
            for (int i = 0; i < 8; i++)
                #pragma unroll
                for (int j = 0; j < 4; j++) acc[rt][i][j] = 0.f;

        #pragma unroll
        for (int nt = 0; nt < 4; nt++) {
            #pragma unroll
            for (int kt = 0; kt < 4; kt++) {
                uint32_t boff = (uint32_t)((nt * 16 + frow) * AS + kt * 16 + fcol) * 2;
                uint32_t Bf[4];
                ldm_x4(Bf, smb + B_OFF + boff);
                #pragma unroll
                for (int rt = 0; rt < 2; rt++) {
                    mma_bf16(acc[rt][2 * nt],     Af[rt][kt], Bf[0], Bf[2]);
                    mma_bf16(acc[rt][2 * nt + 1], Af[rt][kt], Bf[1], Bf[3]);
                }
            }
        }

        // store Y tile as fp16 (half2 per (row, colpair))
        #pragma unroll
        for (int rt = 0; rt < 2; rt++) {
            int row0  = m0 + rt * 16 + g;
            uint32_t node0 = (uint32_t)(tile * 256 + row0);
            #pragma unroll
            for (int nt8 = 0; nt8 < 8; nt8++) {
                int col = nt8 * 8 + tq * 2;
                if (row0 < rows) {
                    __half2 h = __floats2half2_rn(acc[rt][nt8][0], acc[rt][nt8][1]);
                    *(uint32_t*)(g_Yh + ((uint32_t)r * (uint32_t)N + node0) * 64u + col)
                        = *(uint32_t*)&h;
                }
                if (row0 + 8 < rows) {
                    __half2 h = __floats2half2_rn(acc[rt][nt8][2], acc[rt][nt8][3]);
                    *(uint32_t*)(g_Yh + ((uint32_t)r * (uint32_t)N + node0 + 8u) * 64u + col)
                        = *(uint32_t*)&h;
                }
            }
        }
        __syncthreads();   // B consumed before next relation restages
    }
}

// ---- fused edge pass: score, exp, den/cnt, weighted scatter ---------------
__global__ __launch_bounds__(256) void edge_pass(
    const float* __restrict__ ego,
    const int*   __restrict__ heads,
    const int*   __restrict__ tails,
    const int*   __restrict__ etype,
    float*       __restrict__ out,
    int N, int E)
{
    const int gw   = (blockIdx.x * 256 + threadIdx.x) >> 5;
    const int lane = threadIdx.x & 31;
    const int half = lane >> 4;
    const int l2   = lane & 15;
    const unsigned hmask = 0xFFFFu << (half * 16);

    int e = gw * 2 + half;
    if (e >= E) return;

    const int h = heads[e];
    const int t = tails[e];
    const int r = etype[e];

    // 32-bit offsets throughout (Y: 102M elems, ego: 1.6M float4 — both fit)
    uint32_t yidx = ((uint32_t)r * (uint32_t)N + (uint32_t)h) * 64u + (uint32_t)(l2 * 4);
    uint2 yv = *(const uint2*)(g_Yh + yidx);
    float2 f01 = __half22float2(*(__half2*)&yv.x);
    float2 f23 = __half22float2(*(__half2*)&yv.y);

    uint32_t tidx = (uint32_t)t * 16u + (uint32_t)l2;
    float4 t4 = ((const float4*)ego)[tidx];

    float part = f01.x * t4.x + f01.y * t4.y + f23.x * t4.z + f23.y * t4.w;
    part += __shfl_xor_sync(hmask, part, 1);
    part += __shfl_xor_sync(hmask, part, 2);
    part += __shfl_xor_sync(hmask, part, 4);
    part += __shfl_xor_sync(hmask, part, 8);

    float sc = part > 0.0f ? part : 0.01f * part;     // leaky_relu
    float es = __expf(sc);

    if (l2 == 0) {
        float2* dc = &g_dencnt[h];
        asm volatile("red.global.add.v2.f32 [%0], {%1, %2};"
                     :: "l"(dc), "f"(es), "f"(1.0f) : "memory");
    }
    float* op = out + (uint32_t)h * 64u + (uint32_t)(l2 * 4);
    asm volatile("red.global.add.v4.f32 [%0], {%1, %2, %3, %4};"
                 :: "l"(op), "f"(es * t4.x), "f"(es * t4.y),
                    "f"(es * t4.z), "f"(es * t4.w) : "memory");
}

// ---- epilogue: divide by den * max(cnt,1), float4 per thread --------------
__global__ void pass3_mean(float4* __restrict__ out4, int N)
{
    int i = blockIdx.x * blockDim.x + threadIdx.x;    // one float4 (4 elems)
    if (i < N * 16) {
        float2 dc = g_dencnt[i >> 4];
        float s = (dc.y > 0.0f) ? __frcp_rn(dc.x * dc.y) : 0.0f;
        float4 v = out4[i];
        v.x *= s; v.y *= s; v.z *= s; v.w *= s;
        out4[i] = v;
    }
}

// ---------------------------------------------------------------------------
extern "C" void kernel_launch(void* const* d_in, const int* in_sizes, int n_in,
                              void* d_out, int out_size)
{
    const float* ego = (const float*)d_in[0];   // [N,64] f32
    const float* Wg  = (const float*)d_in[1];   // [16,64,64] f32
    const int*   ei  = (const int*)d_in[2];     // [2,E] i32
    const int*   et  = (const int*)d_in[3];     // [E] i32
    float* out = (float*)d_out;

    const int N = in_sizes[0] / 64;
    const int E = in_sizes[3];
    const int* heads = ei;
    const int* tails = ei + E;

    cudaFuncSetAttribute(gemm_transform,
                         cudaFuncAttributeMaxDynamicSharedMemorySize, SMEM_SZ);

    wt_prep<<<16, 256>>>(Wg);

    const int n_out4 = N * 16;                  // out as float4
    const int n_dc4  = (N * 2 + 3) / 4;         // dencnt as float4
    zero_kernel<<<(n_out4 + 255) / 256, 256>>>((float4*)out, n_out4, n_dc4);

    const int tiles = (N + 255) / 256;
    gemm_transform<<<tiles, 256, SMEM_SZ>>>(ego, N);

    edge_pass<<<(E + 15) / 16, 256>>>(ego, heads, tails, et, out, N, E);

    pass3_mean<<<(n_out4 + 255) / 256, 256>>>((float4*)out, N);
}

// round 6
// speedup vs baseline: 4.8130x; 1.1183x over previous
#include <cuda_runtime.h>
#include <cuda_bf16.h>
#include <cuda_fp16.h>
#include <math.h>
#include <stdint.h>

// ---------------------------------------------------------------------------
// Aggregator: relational graph attention, tensor-core (warp mma.sync) version.
//   Y[r]     = ego @ W[r]            (bf16 HMMA, fp32 accumulate, fp16 store)
//   s_e      = leaky_relu( Y[et_e, h_e] . ego[t_e] )
//   out[n]   = sum_e exp(s_e) * ego[t_e]  /  ( den[n] * max(cnt[n],1) )
// den[n] = sum exp over head==n (softmax denom hoisted into the epilogue).
// Edge pass reads Y and a prepared fp16 mirror of ego (halves gather bytes).
// ---------------------------------------------------------------------------

#define N_CAP   131072
#define YROWS   102400               // >= N, multiple of 256
__device__ __half g_Yh[16u * YROWS * 64u];     // [R, N, 64] fp16
__device__ __half g_egoh[(size_t)N_CAP * 64];  // [N, 64] fp16 mirror of ego
__device__ float2 g_dencnt[N_CAP];             // (den, cnt) per head node

// pre-transposed W (row n, col k), padded row stride AS, bf16
#define AS 72
__device__ __nv_bfloat16 g_Wt[16 * 64 * AS];

__device__ __forceinline__ uint32_t smem_u32(const void* p) {
    uint32_t a;
    asm("{ .reg .u64 t; cvta.to.shared.u64 t, %1; cvt.u32.u64 %0, t; }"
        : "=r"(a) : "l"(p));
    return a;
}
__device__ __forceinline__ void ldm_x4(uint32_t* r, uint32_t addr) {
    asm volatile("ldmatrix.sync.aligned.m8n8.x4.shared.b16 {%0,%1,%2,%3}, [%4];"
                 : "=r"(r[0]), "=r"(r[1]), "=r"(r[2]), "=r"(r[3]) : "r"(addr));
}
__device__ __forceinline__ void mma_bf16(float* c, const uint32_t* a,
                                         uint32_t b0, uint32_t b1) {
    asm volatile(
        "mma.sync.aligned.m16n8k16.row.col.f32.bf16.bf16.f32 "
        "{%0,%1,%2,%3}, {%4,%5,%6,%7}, {%8,%9}, {%0,%1,%2,%3};"
        : "+f"(c[0]), "+f"(c[1]), "+f"(c[2]), "+f"(c[3])
        : "r"(a[0]), "r"(a[1]), "r"(a[2]), "r"(a[3]), "r"(b0), "r"(b1));
}
__device__ __forceinline__ uint32_t pack2(float x0, float x1) {
    return ((uint32_t)__bfloat16_as_ushort(__float2bfloat16(x1)) << 16)
         | (uint32_t)__bfloat16_as_ushort(__float2bfloat16(x0));
}

// smem layout (bytes): A = 256 rows x AS halves, then B = 64 rows x AS halves
#define A_OFF   0
#define B_OFF   36864
#define SMEM_SZ (36864 + 9216 + 128)

// ============================ kernels ======================================

// ---- one-time W transpose to bf16 (grid = 16 relations) -------------------
__global__ __launch_bounds__(256) void wt_prep(const float* __restrict__ Wg)
{
    const int r = blockIdx.x;
    for (int idx = threadIdx.x; idx < 4096; idx += 256) {
        int k = idx >> 6, n = idx & 63;             // W[k][n], coalesced read
        float v = Wg[(size_t)r * 4096 + idx];
        g_Wt[r * 64 * AS + n * AS + k] = __float2bfloat16(v);
    }
}

// ---- zero out + dencnt, and build fp16 ego mirror (all coalesced) ---------
__global__ void zero_kernel(float4* __restrict__ out4,
                            const float4* __restrict__ ego4,
                            int n_out4, int n_dc4)
{
    int i = blockIdx.x * blockDim.x + threadIdx.x;
    if (i < n_out4) {
        out4[i] = make_float4(0.f, 0.f, 0.f, 0.f);
        float4 v = ego4[i];
        __half2 h0 = __floats2half2_rn(v.x, v.y);
        __half2 h1 = __floats2half2_rn(v.z, v.w);
        uint2 p = make_uint2(*(uint32_t*)&h0, *(uint32_t*)&h1);
        *(uint2*)(g_egoh + (size_t)i * 4) = p;
    }
    if (i < n_dc4) ((float4*)g_dencnt)[i] = make_float4(0.f, 0.f, 0.f, 0.f);
}

// ---- GEMM: Y[r] = X @ W[r]; 256-row tile per CTA, loop over 16 relations --
__global__ __launch_bounds__(256) void gemm_transform(
    const float* __restrict__ ego, int N)
{
    extern __shared__ __align__(16) char sm[];
    __nv_bfloat16* sh = (__nv_bfloat16*)sm;
    const uint32_t smb = smem_u32(sm);

    const int tid  = threadIdx.x;
    const int wid  = tid >> 5;
    const int lane = tid & 31;
    const int tile = blockIdx.x;
    const int rows = min(256, N - tile * 256);

    // --- stage A tile (ego rows) as bf16, zero-padded ----------------------
    for (int i = tid * 2; i < 256 * 64; i += 512) {
        int row = i >> 6, col = i & 63;
        float v0 = 0.f, v1 = 0.f;
        if (row < rows) {
            const float2 v = *(const float2*)(ego + ((size_t)(tile * 256 + row)) * 64 + col);
            v0 = v.x; v1 = v.y;
        }
        *(uint32_t*)(sh + row * AS + col) = pack2(v0, v1);
    }
    __syncthreads();

    // --- per-warp A fragments: 32 rows (2 x 16) x K=64, loaded once --------
    const int m0   = wid * 32;
    const int frow = (lane & 7) + ((lane >> 3) & 1) * 8;
    const int fcol = (lane >> 4) * 8;
    uint32_t Af[2][4][4];
    #pragma unroll
    for (int rt = 0; rt < 2; rt++)
        #pragma unroll
        for (int kt = 0; kt < 4; kt++) {
            uint32_t off = (uint32_t)((m0 + rt * 16 + frow) * AS + kt * 16 + fcol) * 2;
            ldm_x4(Af[rt][kt], smb + A_OFF + off);
        }

    const int g  = lane >> 2;         // output row within 8-group
    const int tq = lane & 3;          // output col pair

    for (int r = 0; r < 16; r++) {
        // stage B = pre-transposed W_r (pure vector copies)
        {
            const uint4* src = (const uint4*)(g_Wt + r * 64 * AS);
            uint4* dst = (uint4*)(sm + B_OFF);
            #pragma unroll
            for (int i = tid; i < 576; i += 256) dst[i] = src[i];
        }
        __syncthreads();

        float acc[2][8][4];
        #pragma unroll
        for (int rt = 0; rt < 2; rt++)
            #pragma unroll
            for (int i = 0; i < 8; i++)
                #pragma unroll
                for (int j = 0; j < 4; j++) acc[rt][i][j] = 0.f;

        #pragma unroll
        for (int nt = 0; nt < 4; nt++) {
            #pragma unroll
            for (int kt = 0; kt < 4; kt++) {
                uint32_t boff = (uint32_t)((nt * 16 + frow) * AS + kt * 16 + fcol) * 2;
                uint32_t Bf[4];
                ldm_x4(Bf, smb + B_OFF + boff);
                #pragma unroll
                for (int rt = 0; rt < 2; rt++) {
                    mma_bf16(acc[rt][2 * nt],     Af[rt][kt], Bf[0], Bf[2]);
                    mma_bf16(acc[rt][2 * nt + 1], Af[rt][kt], Bf[1], Bf[3]);
                }
            }
        }

        // store Y tile as fp16 (half2 per (row, colpair))
        #pragma unroll
        for (int rt = 0; rt < 2; rt++) {
            int row0  = m0 + rt * 16 + g;
            uint32_t node0 = (uint32_t)(tile * 256 + row0);
            #pragma unroll
            for (int nt8 = 0; nt8 < 8; nt8++) {
                int col = nt8 * 8 + tq * 2;
                if (row0 < rows) {
                    __half2 h = __floats2half2_rn(acc[rt][nt8][0], acc[rt][nt8][1]);
                    *(uint32_t*)(g_Yh + ((uint32_t)r * (uint32_t)N + node0) * 64u + col)
                        = *(uint32_t*)&h;
                }
                if (row0 + 8 < rows) {
                    __half2 h = __floats2half2_rn(acc[rt][nt8][2], acc[rt][nt8][3]);
                    *(uint32_t*)(g_Yh + ((uint32_t)r * (uint32_t)N + node0 + 8u) * 64u + col)
                        = *(uint32_t*)&h;
                }
            }
        }
        __syncthreads();   // B consumed before next relation restages
    }
}

// ---- fused edge pass: 4 edges/warp (2 per half), fp16 gathers -------------
__global__ __launch_bounds__(256) void edge_pass(
    const int*   __restrict__ heads,
    const int*   __restrict__ tails,
    const int*   __restrict__ etype,
    float*       __restrict__ out,
    int N, int E)
{
    const int warp = (blockIdx.x * 256 + threadIdx.x) >> 5;
    const int lane = threadIdx.x & 31;
    const int half = lane >> 4;
    const int l2   = lane & 15;
    const unsigned hmask = 0xFFFFu << (half * 16);

    const int ebase = warp * 4 + half * 2;     // this half-warp: ebase, ebase+1
    if (ebase >= E) return;

    // broadcast int2 loads (ebase is even)
    int2 hh = *(const int2*)(heads + ebase);
    int2 tt = *(const int2*)(tails + ebase);
    int2 rr = *(const int2*)(etype + ebase);
    const bool has1 = (ebase + 1 < E);

    const uint32_t c8 = (uint32_t)(l2 * 4);

    // --- edge 0 gathers -----------------------------------------------------
    uint2 yv0 = *(const uint2*)(g_Yh + ((uint32_t)rr.x * (uint32_t)N + (uint32_t)hh.x) * 64u + c8);
    uint2 tv0 = *(const uint2*)(g_egoh + (uint32_t)tt.x * 64u + c8);
    // --- edge 1 gathers -----------------------------------------------------
    uint2 yv1 = yv0, tv1 = tv0;
    if (has1) {
        yv1 = *(const uint2*)(g_Yh + ((uint32_t)rr.y * (uint32_t)N + (uint32_t)hh.y) * 64u + c8);
        tv1 = *(const uint2*)(g_egoh + (uint32_t)tt.y * 64u + c8);
    }

    float2 y0a = __half22float2(*(__half2*)&yv0.x);
    float2 y0b = __half22float2(*(__half2*)&yv0.y);
    float2 t0a = __half22float2(*(__half2*)&tv0.x);
    float2 t0b = __half22float2(*(__half2*)&tv0.y);
    float2 y1a = __half22float2(*(__half2*)&yv1.x);
    float2 y1b = __half22float2(*(__half2*)&yv1.y);
    float2 t1a = __half22float2(*(__half2*)&tv1.x);
    float2 t1b = __half22float2(*(__half2*)&tv1.y);

    float p0 = y0a.x * t0a.x + y0a.y * t0a.y + y0b.x * t0b.x + y0b.y * t0b.y;
    float p1 = y1a.x * t1a.x + y1a.y * t1a.y + y1b.x * t1b.x + y1b.y * t1b.y;
    #pragma unroll
    for (int o = 1; o < 16; o <<= 1) {
        p0 += __shfl_xor_sync(hmask, p0, o);
        p1 += __shfl_xor_sync(hmask, p1, o);
    }

    float s0 = p0 > 0.f ? p0 : 0.01f * p0;
    float s1 = p1 > 0.f ? p1 : 0.01f * p1;
    float e0 = __expf(s0);
    float e1 = __expf(s1);

    if (l2 == 0) {
        asm volatile("red.global.add.v2.f32 [%0], {%1, %2};"
                     :: "l"(&g_dencnt[hh.x]), "f"(e0), "f"(1.0f) : "memory");
        if (has1)
            asm volatile("red.global.add.v2.f32 [%0], {%1, %2};"
                         :: "l"(&g_dencnt[hh.y]), "f"(e1), "f"(1.0f) : "memory");
    }
    {
        float* op = out + (uint32_t)hh.x * 64u + c8;
        asm volatile("red.global.add.v4.f32 [%0], {%1, %2, %3, %4};"
                     :: "l"(op), "f"(e0 * t0a.x), "f"(e0 * t0a.y),
                        "f"(e0 * t0b.x), "f"(e0 * t0b.y) : "memory");
    }
    if (has1) {
        float* op = out + (uint32_t)hh.y * 64u + c8;
        asm volatile("red.global.add.v4.f32 [%0], {%1, %2, %3, %4};"
                     :: "l"(op), "f"(e1 * t1a.x), "f"(e1 * t1a.y),
                        "f"(e1 * t1b.x), "f"(e1 * t1b.y) : "memory");
    }
}

// ---- epilogue: divide by den * max(cnt,1), float4 per thread --------------
__global__ void pass3_mean(float4* __restrict__ out4, int N)
{
    int i = blockIdx.x * blockDim.x + threadIdx.x;    // one float4 (4 elems)
    if (i < N * 16) {
        float2 dc = g_dencnt[i >> 4];
        float s = (dc.y > 0.0f) ? __frcp_rn(dc.x * dc.y) : 0.0f;
        float4 v = out4[i];
        v.x *= s; v.y *= s; v.z *= s; v.w *= s;
        out4[i] = v;
    }
}

// ---------------------------------------------------------------------------
extern "C" void kernel_launch(void* const* d_in, const int* in_sizes, int n_in,
                              void* d_out, int out_size)
{
    const float* ego = (const float*)d_in[0];   // [N,64] f32
    const float* Wg  = (const float*)d_in[1];   // [16,64,64] f32
    const int*   ei  = (const int*)d_in[2];     // [2,E] i32
    const int*   et  = (const int*)d_in[3];     // [E] i32
    float* out = (float*)d_out;

    const int N = in_sizes[0] / 64;
    const int E = in_sizes[3];
    const int* heads = ei;
    const int* tails = ei + E;

    cudaFuncSetAttribute(gemm_transform,
                         cudaFuncAttributeMaxDynamicSharedMemorySize, SMEM_SZ);

    wt_prep<<<16, 256>>>(Wg);

    const int n_out4 = N * 16;                  // out as float4
    const int n_dc4  = (N * 2 + 3) / 4;         // dencnt as float4
    zero_kernel<<<(n_out4 + 255) / 256, 256>>>((float4*)out, (const float4*)ego,
                                               n_out4, n_dc4);

    const int tiles = (N + 255) / 256;
    gemm_transform<<<tiles, 256, SMEM_SZ>>>(ego, N);

    // 4 edges per warp, 32 per CTA
    edge_pass<<<(E + 31) / 32, 256>>>(heads, tails, et, out, N, E);

    pass3_mean<<<(n_out4 + 255) / 256, 256>>>((float4*)out, N);
}

// round 7
// speedup vs baseline: 4.9117x; 1.0205x over previous
#include <cuda_runtime.h>
#include <cuda_bf16.h>
#include <cuda_fp16.h>
#include <math.h>
#include <stdint.h>

// ---------------------------------------------------------------------------
// Aggregator: relational graph attention, tensor-core (warp mma.sync) version.
//   Y[r]     = ego @ W[r]            (bf16 HMMA, fp32 accumulate, fp16 store)
//   s_e      = leaky_relu( Y[et_e, h_e] . ego[t_e] )
//   out[n]   = sum_e exp(s_e) * ego[t_e]  /  ( den[n] * max(cnt[n],1) )
// den[n] = sum exp over head==n (softmax denom hoisted into the epilogue).
// ---------------------------------------------------------------------------

#define N_CAP   131072
#define YROWS   102400               // >= N, multiple of 256
__device__ __half g_Yh[16u * YROWS * 64u];     // [R, N, 64] fp16
__device__ __half g_egoh[(size_t)N_CAP * 64];  // [N, 64] fp16 mirror of ego
__device__ float2 g_dencnt[N_CAP];             // (den, cnt) per head node

// pre-transposed W (row n, col k), padded row stride AS, bf16
#define AS 72
__device__ __nv_bfloat16 g_Wt[16 * 64 * AS];

__device__ __forceinline__ uint32_t smem_u32(const void* p) {
    uint32_t a;
    asm("{ .reg .u64 t; cvta.to.shared.u64 t, %1; cvt.u32.u64 %0, t; }"
        : "=r"(a) : "l"(p));
    return a;
}
__device__ __forceinline__ void ldm_x4(uint32_t* r, uint32_t addr) {
    asm volatile("ldmatrix.sync.aligned.m8n8.x4.shared.b16 {%0,%1,%2,%3}, [%4];"
                 : "=r"(r[0]), "=r"(r[1]), "=r"(r[2]), "=r"(r[3]) : "r"(addr));
}
__device__ __forceinline__ void mma_bf16(float* c, const uint32_t* a,
                                         uint32_t b0, uint32_t b1) {
    asm volatile(
        "mma.sync.aligned.m16n8k16.row.col.f32.bf16.bf16.f32 "
        "{%0,%1,%2,%3}, {%4,%5,%6,%7}, {%8,%9}, {%0,%1,%2,%3};"
        : "+f"(c[0]), "+f"(c[1]), "+f"(c[2]), "+f"(c[3])
        : "r"(a[0]), "r"(a[1]), "r"(a[2]), "r"(a[3]), "r"(b0), "r"(b1));
}
__device__ __forceinline__ uint32_t pack2(float x0, float x1) {
    return ((uint32_t)__bfloat16_as_ushort(__float2bfloat16(x1)) << 16)
         | (uint32_t)__bfloat16_as_ushort(__float2bfloat16(x0));
}

// smem layout (bytes): A = 256 rows x AS halves; B double-buffered
#define A_OFF   0
#define B_OFF   36864
#define B_BYTES 9216
#define SMEM_SZ (36864 + 2 * B_BYTES + 128)

// ============================ kernels ======================================

// ---- one-time W transpose to bf16 (grid = 16 relations) -------------------
__global__ __launch_bounds__(256) void wt_prep(const float* __restrict__ Wg)
{
    const int r = blockIdx.x;
    for (int idx = threadIdx.x; idx < 4096; idx += 256) {
        int k = idx >> 6, n = idx & 63;             // W[k][n], coalesced read
        float v = Wg[(size_t)r * 4096 + idx];
        g_Wt[r * 64 * AS + n * AS + k] = __float2bfloat16(v);
    }
}

// ---- zero out + dencnt, and build fp16 ego mirror (all coalesced) ---------
__global__ void zero_kernel(float4* __restrict__ out4,
                            const float4* __restrict__ ego4,
                            int n_out4, int n_dc4)
{
    int i = blockIdx.x * blockDim.x + threadIdx.x;
    if (i < n_out4) {
        out4[i] = make_float4(0.f, 0.f, 0.f, 0.f);
        float4 v = ego4[i];
        __half2 h0 = __floats2half2_rn(v.x, v.y);
        __half2 h1 = __floats2half2_rn(v.z, v.w);
        uint2 p = make_uint2(*(uint32_t*)&h0, *(uint32_t*)&h1);
        *(uint2*)(g_egoh + (size_t)i * 4) = p;
    }
    if (i < n_dc4) ((float4*)g_dencnt)[i] = make_float4(0.f, 0.f, 0.f, 0.f);
}

// ---- GEMM: Y[r] = X @ W[r]; 256-row tile per CTA, 16 relations, B dbl-buf -
__global__ __launch_bounds__(256) void gemm_transform(
    const float* __restrict__ ego, int N)
{
    extern __shared__ __align__(16) char sm[];
    __nv_bfloat16* sh = (__nv_bfloat16*)sm;
    const uint32_t smb = smem_u32(sm);

    const int tid  = threadIdx.x;
    const int wid  = tid >> 5;
    const int lane = tid & 31;
    const int tile = blockIdx.x;
    const int rows = min(256, N - tile * 256);

    // --- stage A tile (ego rows) as bf16, zero-padded ----------------------
    for (int i = tid * 2; i < 256 * 64; i += 512) {
        int row = i >> 6, col = i & 63;
        float v0 = 0.f, v1 = 0.f;
        if (row < rows) {
            const float2 v = *(const float2*)(ego + ((size_t)(tile * 256 + row)) * 64 + col);
            v0 = v.x; v1 = v.y;
        }
        *(uint32_t*)(sh + row * AS + col) = pack2(v0, v1);
    }

    // --- stage B(0) directly -----------------------------------------------
    {
        const uint4* src = (const uint4*)g_Wt;
        uint4* dst = (uint4*)(sm + B_OFF);
        #pragma unroll
        for (int k = 0; k < 3; k++) {
            int i = tid + k * 256;
            if (i < 576) dst[i] = src[i];
        }
    }
    __syncthreads();

    // --- per-warp A fragments: 32 rows (2 x 16) x K=64, loaded once --------
    const int m0   = wid * 32;
    const int frow = (lane & 7) + ((lane >> 3) & 1) * 8;
    const int fcol = (lane >> 4) * 8;
    uint32_t Af[2][4][4];
    #pragma unroll
    for (int rt = 0; rt < 2; rt++)
        #pragma unroll
        for (int kt = 0; kt < 4; kt++) {
            uint32_t off = (uint32_t)((m0 + rt * 16 + frow) * AS + kt * 16 + fcol) * 2;
            ldm_x4(Af[rt][kt], smb + A_OFF + off);
        }

    const int g  = lane >> 2;         // output row within 8-group
    const int tq = lane & 3;          // output col pair

    for (int r = 0; r < 16; r++) {
        const uint32_t bcur = B_OFF + (uint32_t)(r & 1) * B_BYTES;

        // prefetch next relation's B into registers (latency overlapped)
        uint4 pf[3];
        if (r < 15) {
            const uint4* src = (const uint4*)(g_Wt + (r + 1) * 64 * AS);
            #pragma unroll
            for (int k = 0; k < 3; k++) {
                int i = tid + k * 256;
                if (i < 576) pf[k] = src[i];
            }
        }

        float acc[2][8][4];
        #pragma unroll
        for (int rt = 0; rt < 2; rt++)
            #pragma unroll
            for (int i = 0; i < 8; i++)
                #pragma unroll
                for (int j = 0; j < 4; j++) acc[rt][i][j] = 0.f;

        #pragma unroll
        for (int nt = 0; nt < 4; nt++) {
            #pragma unroll
            for (int kt = 0; kt < 4; kt++) {
                uint32_t boff = (uint32_t)((nt * 16 + frow) * AS + kt * 16 + fcol) * 2;
                uint32_t Bf[4];
                ldm_x4(Bf, smb + bcur + boff);
                #pragma unroll
                for (int rt = 0; rt < 2; rt++) {
                    mma_bf16(acc[rt][2 * nt],     Af[rt][kt], Bf[0], Bf[2]);
                    mma_bf16(acc[rt][2 * nt + 1], Af[rt][kt], Bf[1], Bf[3]);
                }
            }
        }

        // store Y tile as fp16 (half2 per (row, colpair))
        #pragma unroll
        for (int rt = 0; rt < 2; rt++) {
            int row0  = m0 + rt * 16 + g;
            uint32_t node0 = (uint32_t)(tile * 256 + row0);
            #pragma unroll
            for (int nt8 = 0; nt8 < 8; nt8++) {
                int col = nt8 * 8 + tq * 2;
                if (row0 < rows) {
                    __half2 h = __floats2half2_rn(acc[rt][nt8][0], acc[rt][nt8][1]);
                    *(uint32_t*)(g_Yh + ((uint32_t)r * (uint32_t)N + node0) * 64u + col)
                        = *(uint32_t*)&h;
                }
                if (row0 + 8 < rows) {
                    __half2 h = __floats2half2_rn(acc[rt][nt8][2], acc[rt][nt8][3]);
                    *(uint32_t*)(g_Yh + ((uint32_t)r * (uint32_t)N + node0 + 8u) * 64u + col)
                        = *(uint32_t*)&h;
                }
            }
        }

        // write prefetched B into the other buffer (current buf still in use
        // only by this iteration's ldsm, which is complete)
        if (r < 15) {
            uint4* dst = (uint4*)(sm + B_OFF + (uint32_t)((r + 1) & 1) * B_BYTES);
            #pragma unroll
            for (int k = 0; k < 3; k++) {
                int i = tid + k * 256;
                if (i < 576) dst[i] = pf[k];
            }
        }
        __syncthreads();   // one barrier per relation
    }
}

// ---- fused edge pass: 8 edges/warp (4 per half), fp16 gathers -------------
__global__ __launch_bounds__(256) void edge_pass(
    const int*   __restrict__ heads,
    const int*   __restrict__ tails,
    const int*   __restrict__ etype,
    float*       __restrict__ out,
    int N, int E)
{
    const int warp = (blockIdx.x * 256 + threadIdx.x) >> 5;
    const int lane = threadIdx.x & 31;
    const int half = lane >> 4;
    const int l2   = lane & 15;
    const unsigned hmask = 0xFFFFu << (half * 16);

    const int ebase = warp * 8 + half * 4;     // this half-warp: 4 edges
    if (ebase >= E) return;

    int4 hh, tt, rr;
    if (ebase + 3 < E) {
        hh = *(const int4*)(heads + ebase);
        tt = *(const int4*)(tails + ebase);
        rr = *(const int4*)(etype + ebase);
    } else {
        int* hp = (int*)&hh; int* tp = (int*)&tt; int* rp = (int*)&rr;
        #pragma unroll
        for (int j = 0; j < 4; j++) {
            int e = min(ebase + j, E - 1);
            hp[j] = heads[e]; tp[j] = tails[e]; rp[j] = etype[e];
        }
    }
    const int* hp = (const int*)&hh;
    const int* tp = (const int*)&tt;
    const int* rp = (const int*)&rr;

    const uint32_t c8 = (uint32_t)(l2 * 4);

    // issue all gathers first (8 independent loads in flight)
    uint2 yv[4], tv[4];
    #pragma unroll
    for (int j = 0; j < 4; j++) {
        yv[j] = *(const uint2*)(g_Yh + ((uint32_t)rp[j] * (uint32_t)N + (uint32_t)hp[j]) * 64u + c8);
        tv[j] = *(const uint2*)(g_egoh + (uint32_t)tp[j] * 64u + c8);
    }

    float p[4];
    float tf[4][4];
    #pragma unroll
    for (int j = 0; j < 4; j++) {
        float2 ya = __half22float2(*(__half2*)&yv[j].x);
        float2 yb = __half22float2(*(__half2*)&yv[j].y);
        float2 ta = __half22float2(*(__half2*)&tv[j].x);
        float2 tb = __half22float2(*(__half2*)&tv[j].y);
        tf[j][0] = ta.x; tf[j][1] = ta.y; tf[j][2] = tb.x; tf[j][3] = tb.y;
        p[j] = ya.x * ta.x + ya.y * ta.y + yb.x * tb.x + yb.y * tb.y;
    }
    #pragma unroll
    for (int o = 1; o < 16; o <<= 1) {
        #pragma unroll
        for (int j = 0; j < 4; j++)
            p[j] += __shfl_xor_sync(hmask, p[j], o);
    }

    float ex[4];
    #pragma unroll
    for (int j = 0; j < 4; j++) {
        float s = p[j] > 0.f ? p[j] : 0.01f * p[j];
        ex[j] = __expf(s);
    }

    #pragma unroll
    for (int j = 0; j < 4; j++) {
        if (ebase + j >= E) break;
        if (l2 == 0)
            asm volatile("red.global.add.v2.f32 [%0], {%1, %2};"
                         :: "l"(&g_dencnt[hp[j]]), "f"(ex[j]), "f"(1.0f) : "memory");
        float* op = out + (uint32_t)hp[j] * 64u + c8;
        asm volatile("red.global.add.v4.f32 [%0], {%1, %2, %3, %4};"
                     :: "l"(op), "f"(ex[j] * tf[j][0]), "f"(ex[j] * tf[j][1]),
                        "f"(ex[j] * tf[j][2]), "f"(ex[j] * tf[j][3]) : "memory");
    }
}

// ---- epilogue: divide by den * max(cnt,1), float4 per thread --------------
__global__ void pass3_mean(float4* __restrict__ out4, int N)
{
    int i = blockIdx.x * blockDim.x + threadIdx.x;    // one float4 (4 elems)
    if (i < N * 16) {
        float2 dc = g_dencnt[i >> 4];
        float s = (dc.y > 0.0f) ? __frcp_rn(dc.x * dc.y) : 0.0f;
        float4 v = out4[i];
        v.x *= s; v.y *= s; v.z *= s; v.w *= s;
        out4[i] = v;
    }
}

// ---------------------------------------------------------------------------
extern "C" void kernel_launch(void* const* d_in, const int* in_sizes, int n_in,
                              void* d_out, int out_size)
{
    const float* ego = (const float*)d_in[0];   // [N,64] f32
    const float* Wg  = (const float*)d_in[1];   // [16,64,64] f32
    const int*   ei  = (const int*)d_in[2];     // [2,E] i32
    const int*   et  = (const int*)d_in[3];     // [E] i32
    float* out = (float*)d_out;

    const int N = in_sizes[0] / 64;
    const int E = in_sizes[3];
    const int* heads = ei;
    const int* tails = ei + E;

    cudaFuncSetAttribute(gemm_transform,
                         cudaFuncAttributeMaxDynamicSharedMemorySize, SMEM_SZ);

    wt_prep<<<16, 256>>>(Wg);

    const int n_out4 = N * 16;                  // out as float4
    const int n_dc4  = (N * 2 + 3) / 4;         // dencnt as float4
    zero_kernel<<<(n_out4 + 255) / 256, 256>>>((float4*)out, (const float4*)ego,
                                               n_out4, n_dc4);

    const int tiles = (N + 255) / 256;
    gemm_transform<<<tiles, 256, SMEM_SZ>>>(ego, N);

    // 8 edges per warp, 64 per CTA
    edge_pass<<<(E + 63) / 64, 256>>>(heads, tails, et, out, N, E);

    pass3_mean<<<(n_out4 + 255) / 256, 256>>>((float4*)out, N);
}

// round 8
// speedup vs baseline: 5.1921x; 1.0571x over previous
#include <cuda_runtime.h>
#include <cuda_bf16.h>
#include <cuda_fp16.h>
#include <math.h>
#include <stdint.h>

// ---------------------------------------------------------------------------
// Aggregator: relational graph attention, tensor-core (warp mma.sync) version.
//   Y[r]     = ego @ W[r]            (bf16 HMMA, fp32 accumulate, fp16 store)
//   s_e      = leaky_relu( Y[et_e, h_e] . ego[t_e] )
//   out[n]   = sum_e exp(s_e) * ego[t_e]  /  ( den[n] * max(cnt[n],1) )
// ---------------------------------------------------------------------------

#define N_CAP   131072
#define YROWS   102400               // >= N, multiple of 128
__device__ __half g_Yh[16u * YROWS * 64u];     // [R, N, 64] fp16
__device__ __half g_egoh[(size_t)N_CAP * 64];  // [N, 64] fp16 mirror of ego
__device__ float2 g_dencnt[N_CAP];             // (den, cnt) per head node

// pre-transposed W (row n, col k), padded row stride AS, bf16
#define AS 72
__device__ __nv_bfloat16 g_Wt[16 * 64 * AS];

__device__ __forceinline__ uint32_t smem_u32(const void* p) {
    uint32_t a;
    asm("{ .reg .u64 t; cvta.to.shared.u64 t, %1; cvt.u32.u64 %0, t; }"
        : "=r"(a) : "l"(p));
    return a;
}
__device__ __forceinline__ void ldm_x4(uint32_t* r, uint32_t addr) {
    asm volatile("ldmatrix.sync.aligned.m8n8.x4.shared.b16 {%0,%1,%2,%3}, [%4];"
                 : "=r"(r[0]), "=r"(r[1]), "=r"(r[2]), "=r"(r[3]) : "r"(addr));
}
__device__ __forceinline__ void mma_bf16(float* c, const uint32_t* a,
                                         uint32_t b0, uint32_t b1) {
    asm volatile(
        "mma.sync.aligned.m16n8k16.row.col.f32.bf16.bf16.f32 "
        "{%0,%1,%2,%3}, {%4,%5,%6,%7}, {%8,%9}, {%0,%1,%2,%3};"
        : "+f"(c[0]), "+f"(c[1]), "+f"(c[2]), "+f"(c[3])
        : "r"(a[0]), "r"(a[1]), "r"(a[2]), "r"(a[3]), "r"(b0), "r"(b1));
}
__device__ __forceinline__ uint32_t pack2(float x0, float x1) {
    return ((uint32_t)__bfloat16_as_ushort(__float2bfloat16(x1)) << 16)
         | (uint32_t)__bfloat16_as_ushort(__float2bfloat16(x0));
}

// smem layout (bytes): A = 128 rows x AS halves (18432), then B (9216)
#define A_OFF   0
#define B_OFF   18432
#define SMEM_SZ (18432 + 9216 + 128)

// ============================ kernels ======================================

// ---- zero out + dencnt + fp16 ego mirror; blocks 0..15 also prep W --------
__global__ void zero_kernel(float4* __restrict__ out4,
                            const float4* __restrict__ ego4,
                            const float* __restrict__ Wg,
                            int n_out4, int n_dc4)
{
    int i = blockIdx.x * blockDim.x + threadIdx.x;
    if (i < n_out4) {
        out4[i] = make_float4(0.f, 0.f, 0.f, 0.f);
        float4 v = ego4[i];
        __half2 h0 = __floats2half2_rn(v.x, v.y);
        __half2 h1 = __floats2half2_rn(v.z, v.w);
        uint2 p = make_uint2(*(uint32_t*)&h0, *(uint32_t*)&h1);
        *(uint2*)(g_egoh + (size_t)i * 4) = p;
    }
    if (i < n_dc4) ((float4*)g_dencnt)[i] = make_float4(0.f, 0.f, 0.f, 0.f);

    if (blockIdx.x < 16) {           // W transpose to bf16, padded stride
        const int r = blockIdx.x;
        for (int idx = threadIdx.x; idx < 4096; idx += 256) {
            int k = idx >> 6, n = idx & 63;          // W[k][n], coalesced read
            float v = Wg[(size_t)r * 4096 + idx];
            g_Wt[r * 64 * AS + n * AS + k] = __float2bfloat16(v);
        }
    }
}

// ---- GEMM: Y[r] = X @ W[r]; 128-row tile per CTA (reg-occupancy friendly) -
__global__ __launch_bounds__(256) void gemm_transform(
    const float* __restrict__ ego, int N)
{
    extern __shared__ __align__(16) char sm[];
    __nv_bfloat16* sh = (__nv_bfloat16*)sm;
    const uint32_t smb = smem_u32(sm);

    const int tid  = threadIdx.x;
    const int wid  = tid >> 5;
    const int lane = tid & 31;
    const int tile = blockIdx.x;
    const int rows = min(128, N - tile * 128);

    // --- stage A tile (ego rows) as bf16, zero-padded ----------------------
    for (int i = tid * 2; i < 128 * 64; i += 512) {
        int row = i >> 6, col = i & 63;
        float v0 = 0.f, v1 = 0.f;
        if (row < rows) {
            const float2 v = *(const float2*)(ego + ((size_t)(tile * 128 + row)) * 64 + col);
            v0 = v.x; v1 = v.y;
        }
        *(uint32_t*)(sh + row * AS + col) = pack2(v0, v1);
    }
    __syncthreads();

    // --- per-warp A fragment: 16 rows x K=64, loaded once ------------------
    const int m0   = wid * 16;
    const int frow = (lane & 7) + ((lane >> 3) & 1) * 8;
    const int fcol = (lane >> 4) * 8;
    uint32_t Af[4][4];
    #pragma unroll
    for (int kt = 0; kt < 4; kt++) {
        uint32_t off = (uint32_t)((m0 + frow) * AS + kt * 16 + fcol) * 2;
        ldm_x4(Af[kt], smb + A_OFF + off);
    }

    const int g  = lane >> 2;         // output row within 8-group
    const int tq = lane & 3;          // output col pair

    for (int r = 0; r < 16; r++) {
        // stage B = pre-transposed W_r (pure vector copies)
        {
            const uint4* src = (const uint4*)(g_Wt + r * 64 * AS);
            uint4* dst = (uint4*)(sm + B_OFF);
            #pragma unroll
            for (int k = 0; k < 3; k++) {
                int i = tid + k * 256;
                if (i < 576) dst[i] = src[i];
            }
        }
        __syncthreads();

        float acc[8][4];
        #pragma unroll
        for (int i = 0; i < 8; i++)
            #pragma unroll
            for (int j = 0; j < 4; j++) acc[i][j] = 0.f;

        #pragma unroll
        for (int nt = 0; nt < 4; nt++) {
            #pragma unroll
            for (int kt = 0; kt < 4; kt++) {
                uint32_t boff = (uint32_t)((nt * 16 + frow) * AS + kt * 16 + fcol) * 2;
                uint32_t Bf[4];
                ldm_x4(Bf, smb + B_OFF + boff);
                mma_bf16(acc[2 * nt],     Af[kt], Bf[0], Bf[2]);
                mma_bf16(acc[2 * nt + 1], Af[kt], Bf[1], Bf[3]);
            }
        }

        // store Y tile as fp16 (half2 per (row, colpair))
        int row0  = m0 + g;
        uint32_t node0 = (uint32_t)(tile * 128 + row0);
        #pragma unroll
        for (int nt8 = 0; nt8 < 8; nt8++) {
            int col = nt8 * 8 + tq * 2;
            if (row0 < rows) {
                __half2 h = __floats2half2_rn(acc[nt8][0], acc[nt8][1]);
                *(uint32_t*)(g_Yh + ((uint32_t)r * (uint32_t)N + node0) * 64u + col)
                    = *(uint32_t*)&h;
            }
            if (row0 + 8 < rows) {
                __half2 h = __floats2half2_rn(acc[nt8][2], acc[nt8][3]);
                *(uint32_t*)(g_Yh + ((uint32_t)r * (uint32_t)N + node0 + 8u) * 64u + col)
                    = *(uint32_t*)&h;
            }
        }
        __syncthreads();   // B consumed before next relation restages
    }
}

// ---- fused edge pass: 8 edges/warp (4 per half), fp16 gathers -------------
__global__ __launch_bounds__(256) void edge_pass(
    const int*   __restrict__ heads,
    const int*   __restrict__ tails,
    const int*   __restrict__ etype,
    float*       __restrict__ out,
    int N, int E)
{
    const int warp = (blockIdx.x * 256 + threadIdx.x) >> 5;
    const int lane = threadIdx.x & 31;
    const int half = lane >> 4;
    const int l2   = lane & 15;
    const unsigned hmask = 0xFFFFu << (half * 16);

    const int ebase = warp * 8 + half * 4;     // this half-warp: 4 edges
    if (ebase >= E) return;

    int4 hh, tt, rr;
    if (ebase + 3 < E) {
        hh = *(const int4*)(heads + ebase);
        tt = *(const int4*)(tails + ebase);
        rr = *(const int4*)(etype + ebase);
    } else {
        int* hp = (int*)&hh; int* tp = (int*)&tt; int* rp = (int*)&rr;
        #pragma unroll
        for (int j = 0; j < 4; j++) {
            int e = min(ebase + j, E - 1);
            hp[j] = heads[e]; tp[j] = tails[e]; rp[j] = etype[e];
        }
    }
    const int* hp = (const int*)&hh;
    const int* tp = (const int*)&tt;
    const int* rp = (const int*)&rr;

    const uint32_t c8 = (uint32_t)(l2 * 4);

    // issue all gathers first (8 independent loads in flight)
    uint2 yv[4], tv[4];
    #pragma unroll
    for (int j = 0; j < 4; j++) {
        yv[j] = *(const uint2*)(g_Yh + ((uint32_t)rp[j] * (uint32_t)N + (uint32_t)hp[j]) * 64u + c8);
        tv[j] = *(const uint2*)(g_egoh + (uint32_t)tp[j] * 64u + c8);
    }

    float p[4];
    float tf[4][4];
    #pragma unroll
    for (int j = 0; j < 4; j++) {
        float2 ya = __half22float2(*(__half2*)&yv[j].x);
        float2 yb = __half22float2(*(__half2*)&yv[j].y);
        float2 ta = __half22float2(*(__half2*)&tv[j].x);
        float2 tb = __half22float2(*(__half2*)&tv[j].y);
        tf[j][0] = ta.x; tf[j][1] = ta.y; tf[j][2] = tb.x; tf[j][3] = tb.y;
        p[j] = ya.x * ta.x + ya.y * ta.y + yb.x * tb.x + yb.y * tb.y;
    }
    #pragma unroll
    for (int o = 1; o < 16; o <<= 1) {
        #pragma unroll
        for (int j = 0; j < 4; j++)
            p[j] += __shfl_xor_sync(hmask, p[j], o);
    }

    float ex[4];
    #pragma unroll
    for (int j = 0; j < 4; j++) {
        float s = p[j] > 0.f ? p[j] : 0.01f * p[j];
        ex[j] = __expf(s);
    }

    #pragma unroll
    for (int j = 0; j < 4; j++) {
        if (ebase + j >= E) break;
        if (l2 == 0)
            asm volatile("red.global.add.v2.f32 [%0], {%1, %2};"
                         :: "l"(&g_dencnt[hp[j]]), "f"(ex[j]), "f"(1.0f) : "memory");
        float* op = out + (uint32_t)hp[j] * 64u + c8;
        asm volatile("red.global.add.v4.f32 [%0], {%1, %2, %3, %4};"
                     :: "l"(op), "f"(ex[j] * tf[j][0]), "f"(ex[j] * tf[j][1]),
                        "f"(ex[j] * tf[j][2]), "f"(ex[j] * tf[j][3]) : "memory");
    }
}

// ---- epilogue: divide by den * max(cnt,1), float4 per thread --------------
__global__ void pass3_mean(float4* __restrict__ out4, int N)
{
    int i = blockIdx.x * blockDim.x + threadIdx.x;    // one float4 (4 elems)
    if (i < N * 16) {
        float2 dc = g_dencnt[i >> 4];
        float s = (dc.y > 0.0f) ? __frcp_rn(dc.x * dc.y) : 0.0f;
        float4 v = out4[i];
        v.x *= s; v.y *= s; v.z *= s; v.w *= s;
        out4[i] = v;
    }
}

// ---------------------------------------------------------------------------
extern "C" void kernel_launch(void* const* d_in, const int* in_sizes, int n_in,
                              void* d_out, int out_size)
{
    const float* ego = (const float*)d_in[0];   // [N,64] f32
    const float* Wg  = (const float*)d_in[1];   // [16,64,64] f32
    const int*   ei  = (const int*)d_in[2];     // [2,E] i32
    const int*   et  = (const int*)d_in[3];     // [E] i32
    float* out = (float*)d_out;

    const int N = in_sizes[0] / 64;
    const int E = in_sizes[3];
    const int* heads = ei;
    const int* tails = ei + E;

    cudaFuncSetAttribute(gemm_transform,
                         cudaFuncAttributeMaxDynamicSharedMemorySize, SMEM_SZ);

    const int n_out4 = N * 16;                  // out as float4
    const int n_dc4  = (N * 2 + 3) / 4;         // dencnt as float4
    zero_kernel<<<(n_out4 + 255) / 256, 256>>>((float4*)out, (const float4*)ego,
                                               Wg, n_out4, n_dc4);

    const int tiles = (N + 127) / 128;
    gemm_transform<<<tiles, 256, SMEM_SZ>>>(ego, N);

    // 8 edges per warp, 64 per CTA
    edge_pass<<<(E + 63) / 64, 256>>>(heads, tails, et, out, N, E);

    pass3_mean<<<(n_out4 + 255) / 256, 256>>>((float4*)out, N);
}